// round 16
// baseline (speedup 1.0000x reference)
#include <cuda_runtime.h>

#define DIM   96
#define DIM3  (DIM * DIM * DIM)   // 884736
#define CH    24
#define CH4   (CH / 4)            // 6 float4 per voxel row
#define FEAT4 (DIM3 * CH4)        // 5308416 float4 elements per volume

#define B         256
#define FILL_ILP  4
#define FILL_THREADS (FEAT4 / FILL_ILP)          // 1327104 (exact)
#define FILL_BLOCKS  (FILL_THREADS / B)          // 5184 (exact)
#define MISC_BLOCKS  (DIM3 / 4 / B)              // 864 (exact, 4 voxels/thread)

#define PRE_BLOCKS 592                           // 4 per SM on 148 SMs: always co-resident

// ---------------- scratch (device globals; no allocation allowed) ----------------
// Packed winner pair: .x = win_cur (row or -1), .y = win_glb ((row<<1)|nz or -1)
__device__ int2          g_win_cg[DIM3];
__device__ int           g_win_tgt[DIM3];
__device__ unsigned char g_valid_vol[DIM3];
__device__ unsigned char g_occ[DIM3];

// software grid barrier state (gen monotonically increases across replays;
// comparisons are relative, so replay-to-replay state carry is benign)
__device__ unsigned int  g_bar_count = 0;
__device__ unsigned int  g_bar_gen   = 0;

__device__ __forceinline__ void grid_barrier() {
    __syncthreads();
    if (threadIdx.x == 0) {
        __threadfence();                                   // publish this block's writes
        unsigned int gen = *((volatile unsigned int*)&g_bar_gen);
        unsigned int arrived = atomicAdd(&g_bar_count, 1);
        if (arrived == PRE_BLOCKS - 1) {
            g_bar_count = 0;
            __threadfence();
            atomicAdd(&g_bar_gen, 1);                      // release
        } else {
            while (*((volatile unsigned int*)&g_bar_gen) == gen) { }
        }
        __threadfence();                                   // acquire
    }
    __syncthreads();
}

// ---------------- persistent pre-kernel: init -> scatter_a -> scatter_glb ----------------
// atomicMax(row-priority) reproduces XLA's sequential last-write-wins.
__global__ void __launch_bounds__(B) k_pre(const int* __restrict__ cc,
                                           const int* __restrict__ gm,
                                           const int* __restrict__ occ,
                                           const int* __restrict__ gct,
                                           const int* __restrict__ ct,
                                           const int* __restrict__ gc,
                                           const float4* __restrict__ glb_vals,
                                           const int* __restrict__ origin,
                                           float* __restrict__ out_vt,
                                           float* __restrict__ out_valid,
                                           float* __restrict__ out_near,
                                           int n_cur, int n_g, int n_c, int n_glb) {
    const int tid = blockIdx.x * B + threadIdx.x;
    const int nthr = PRE_BLOCKS * B;

    // ---- phase 0: scratch reset (vectorized) ----
    {
        const int4 m1 = make_int4(-1, -1, -1, -1);
        for (int i = tid; i < DIM3 / 2; i += nthr)
            ((int4*)g_win_cg)[i] = m1;                 // 2 voxels per int4
        for (int i = tid; i < DIM3 / 4; i += nthr) {
            ((int4*)g_win_tgt)[i] = m1;
            ((int*)g_valid_vol)[i] = 0;
            ((int*)g_occ)[i] = 0;
        }
    }
    grid_barrier();

    // ---- phase 1: current-fragment scatter + target scatters ----
    {
        int n_a = n_cur + n_g + n_c;
        for (int i = tid; i < n_a; i += nthr) {
            if (i < n_cur) {
                int x = cc[3 * i], y = cc[3 * i + 1], z = cc[3 * i + 2];
                int v = (x * DIM + y) * DIM + z;
                atomicMax(&g_win_cg[v].x, i);
                if (gm[i] != 0)  g_valid_vol[v] = 1;
                if (occ[i] != 0) g_occ[v] = 1;
                continue;
            }
            int j = i - n_cur;
            if (j < n_g) {
                // global target rows scattered first -> lower priority band [0, n_g)
                int x = gct[3 * j]     - origin[0];
                int y = gct[3 * j + 1] - origin[1];
                int z = gct[3 * j + 2] - origin[2];
                bool inb = ((unsigned)x < DIM) && ((unsigned)y < DIM) && ((unsigned)z < DIM);
                out_vt[j] = inb ? 1.0f : 0.0f;
                if (inb) atomicMax(&g_win_tgt[(x * DIM + y) * DIM + z], j);
            } else {
                // current-fragment target rows scattered second -> win ties
                int t = j - n_g;
                int x = ct[3 * t], y = ct[3 * t + 1], z = ct[3 * t + 2];
                atomicMax(&g_win_tgt[(x * DIM + y) * DIM + z], n_g + t);
            }
        }
    }
    grid_barrier();

    // ---- phase 2: global-row scatter (needs valid_vol from phase 1) ----
    for (int i = tid; i < n_glb; i += nthr) {
        int x = gc[3 * i]     - origin[0];
        int y = gc[3 * i + 1] - origin[1];
        int z = gc[3 * i + 2] - origin[2];
        bool inb = ((unsigned)x < DIM) && ((unsigned)y < DIM) && ((unsigned)z < DIM);
        bool valid = false;
        if (inb) {
            int v = (x * DIM + y) * DIM + z;
            valid = (g_valid_vol[v] != 0);
            if (valid) {
                bool nz = false;
                #pragma unroll
                for (int q = 0; q < CH4; ++q) {
                    float4 r = glb_vals[i * CH4 + q];
                    nz |= (r.x != 0.0f) | (r.y != 0.0f) | (r.z != 0.0f) | (r.w != 0.0f);
                }
                atomicMax(&g_win_cg[v].y, (i << 1) | (nz ? 1 : 0));
            }
        }
        out_valid[i] = valid ? 1.0f : 0.0f;
        out_near[i]  = (inb && !valid) ? 1.0f : 0.0f;
    }
}

// ---------------- fused dense fill (byte-identical to R8 best) ----------------
// Misc blocks FIRST (no ragged tail), vectorized 4 voxels/thread. Fill blocks:
// 4-way ILP over grid-strided float4 slices; one LDG.64 fetches both winners;
// __stcs streaming stores keep tables/winners L2-resident (output write-once).
__global__ void k_fill(const float4* __restrict__ cur_vals,
                       const float4* __restrict__ glb_vals,
                       const float* __restrict__ tsdf_tgt,
                       const float* __restrict__ gtsdf_tgt,
                       float4* __restrict__ out_cur,
                       float4* __restrict__ out_glb,
                       float4* __restrict__ out_tgt,
                       float4* __restrict__ out_mask,
                       int n_gtgt) {
    int b = blockIdx.x;
    if (b >= MISC_BLOCKS) {
        int base = (b - MISC_BLOCKS) * B + threadIdx.x;
        const float4 zero = make_float4(0.f, 0.f, 0.f, 0.f);
        int e[FILL_ILP];
        int2 w[FILL_ILP];
        #pragma unroll
        for (int k = 0; k < FILL_ILP; ++k) {
            e[k] = base + k * FILL_THREADS;
            w[k] = g_win_cg[e[k] / CH4];
        }
        #pragma unroll
        for (int k = 0; k < FILL_ILP; ++k) {
            int v = e[k] / CH4;
            int q = e[k] - v * CH4;
            float4 rc = (w[k].x >= 0) ? cur_vals[w[k].x * CH4 + q] : zero;
            float4 rg = (w[k].y >= 0) ? glb_vals[(w[k].y >> 1) * CH4 + q] : zero;
            __stcs(&out_cur[e[k]], rc);
            __stcs(&out_glb[e[k]], rg);
        }
        return;
    }
    // misc: 4 voxels per thread; int4 loads cover 2 packed winner pairs each
    int t4 = b * B + threadIdx.x;            // float4 index into out_tgt/out_mask
    int4 wt = ((const int4*)g_win_tgt)[t4];
    int4 wp0 = ((const int4*)g_win_cg)[t4 * 2 + 0];   // voxels v0,v0+1: (cur,glb,cur,glb)
    int4 wp1 = ((const int4*)g_win_cg)[t4 * 2 + 1];   // voxels v0+2,v0+3
    unsigned int occ4 = ((const unsigned int*)g_occ)[t4];

    float tv[4];
    int wts[4] = {wt.x, wt.y, wt.z, wt.w};
    #pragma unroll
    for (int k = 0; k < 4; ++k) {
        int w = wts[k];
        if (w < 0)            tv[k] = 1.0f;
        else if (w >= n_gtgt) tv[k] = tsdf_tgt[w - n_gtgt];
        else                  tv[k] = gtsdf_tgt[w];
    }
    __stcs(&out_tgt[t4], make_float4(tv[0], tv[1], tv[2], tv[3]));

    int wgs[4] = {wp0.y, wp0.w, wp1.y, wp1.w};
    float mv[4];
    #pragma unroll
    for (int k = 0; k < 4; ++k) {
        bool m = ((occ4 >> (8 * k)) & 0xFF) != 0;
        m |= (wgs[k] >= 0) && (wgs[k] & 1);
        mv[k] = m ? 1.0f : 0.0f;
    }
    __stcs(&out_mask[t4], make_float4(mv[0], mv[1], mv[2], mv[3]));
}

// ---------------- launch ----------------

extern "C" void kernel_launch(void* const* d_in, const int* in_sizes, int n_in,
                              void* d_out, int out_size) {
    const int*   cur_coords = (const int*)d_in[0];
    const float* cur_vals   = (const float*)d_in[1];
    const int*   glb_coords = (const int*)d_in[2];
    const float* glb_vals   = (const float*)d_in[3];
    const int*   ct_coords  = (const int*)d_in[4];
    const float* tsdf_tgt   = (const float*)d_in[5];
    const int*   gct_coords = (const int*)d_in[6];
    const float* gtsdf_tgt  = (const float*)d_in[7];
    const int*   origin     = (const int*)d_in[8];
    const int*   grid_mask  = (const int*)d_in[9];   // bool promoted to 4-byte
    const int*   occupancy  = (const int*)d_in[10];  // bool promoted to 4-byte

    const int n_cur  = in_sizes[0] / 3;
    const int n_glb  = in_sizes[2] / 3;
    const int n_tgt  = in_sizes[4] / 3;
    const int n_gtgt = in_sizes[6] / 3;

    float* out = (float*)d_out;
    // output layout: tuple order, flattened, float32
    float* out_mask  = out;                          // DIM3
    float* out_cur   = out_mask + DIM3;              // DIM3*CH
    float* out_glb   = out_cur + (size_t)DIM3 * CH;  // DIM3*CH
    float* out_tgt   = out_glb + (size_t)DIM3 * CH;  // DIM3
    float* out_valid = out_tgt + DIM3;               // n_glb
    float* out_vt    = out_valid + n_glb;            // n_gtgt
    float* out_near  = out_vt + n_gtgt;              // n_glb

    k_pre<<<PRE_BLOCKS, B>>>(cur_coords, grid_mask, occupancy,
                             gct_coords, ct_coords,
                             glb_coords, (const float4*)glb_vals, origin,
                             out_vt, out_valid, out_near,
                             n_cur, n_gtgt, n_tgt, n_glb);

    k_fill<<<MISC_BLOCKS + FILL_BLOCKS, B>>>((const float4*)cur_vals, (const float4*)glb_vals,
                                             tsdf_tgt, gtsdf_tgt,
                                             (float4*)out_cur, (float4*)out_glb,
                                             (float4*)out_tgt, (float4*)out_mask, n_gtgt);
}

// round 17
// speedup vs baseline: 1.1123x; 1.1123x over previous
#include <cuda_runtime.h>

#define DIM   96
#define DIM3  (DIM * DIM * DIM)   // 884736
#define CH    24
#define CH4   (CH / 4)            // 6 float4 per voxel row
#define FEAT4 (DIM3 * CH4)        // 5308416 float4 elements per volume

#define B         256
#define FILL_ILP  4
#define FILL_THREADS (FEAT4 / FILL_ILP)          // 1327104 (exact)
#define FILL_BLOCKS  (FILL_THREADS / B)          // 5184 (exact)
#define MISC_BLOCKS  (DIM3 / 4 / B)              // 864 (exact, 4 voxels/thread)

// ---------------- scratch (device globals; no allocation allowed) ----------------
// Packed winner pair: .x = win_cur (row or -1), .y = win_glb ((row<<1)|nz or -1)
__device__ int2          g_win_cg[DIM3];
__device__ int           g_win_tgt[DIM3];
__device__ unsigned char g_valid_vol[DIM3];
__device__ unsigned char g_occ[DIM3];

// ---------------- kernels ----------------

// Vectorized scratch reset: winners = -1 (int4), flags = 0.
__global__ void k_init() {
    int i = blockIdx.x * blockDim.x + threadIdx.x;
    const int4 m1 = make_int4(-1, -1, -1, -1);
    if (i < DIM3 / 2)
        ((int4*)g_win_cg)[i] = m1;          // 2 voxels per int4
    if (i < DIM3 / 4) {
        ((int4*)g_win_tgt)[i] = m1;
        ((int*)g_valid_vol)[i] = 0;
        ((int*)g_occ)[i] = 0;
    }
}

// Fused current-fragment + target scatters, 2 items per thread (grid-split
// halves -> independent load->atomic chains, 2x MLP for this latency-bound
// kernel). atomicMax(row-priority) == XLA's sequential last-write-wins.
__global__ void k_scatter_a(const int* __restrict__ cc,
                            const int* __restrict__ gm,
                            const int* __restrict__ occ,
                            const int* __restrict__ gct,
                            const int* __restrict__ ct,
                            const int* __restrict__ origin,
                            float* __restrict__ out_vt,
                            int n_cur, int n_g, int n_c) {
    const int n_a = n_cur + n_g + n_c;
    const int half = (n_a + 1) / 2;
    const int t = blockIdx.x * blockDim.x + threadIdx.x;
    #pragma unroll
    for (int k = 0; k < 2; ++k) {
        int i = t + k * half;
        if (i >= n_a) break;
        if (i < n_cur) {
            int x = cc[3 * i], y = cc[3 * i + 1], z = cc[3 * i + 2];
            int v = (x * DIM + y) * DIM + z;
            atomicMax(&g_win_cg[v].x, i);
            if (gm[i] != 0)  g_valid_vol[v] = 1;
            if (occ[i] != 0) g_occ[v] = 1;
            continue;
        }
        int j = i - n_cur;
        if (j < n_g) {
            // global target rows scattered first -> lower priority band [0, n_g)
            int x = gct[3 * j]     - origin[0];
            int y = gct[3 * j + 1] - origin[1];
            int z = gct[3 * j + 2] - origin[2];
            bool inb = ((unsigned)x < DIM) && ((unsigned)y < DIM) && ((unsigned)z < DIM);
            out_vt[j] = inb ? 1.0f : 0.0f;
            if (inb) atomicMax(&g_win_tgt[(x * DIM + y) * DIM + z], j);
        } else {
            // current-fragment target rows scattered second -> win ties
            int tt = j - n_g;
            int x = ct[3 * tt], y = ct[3 * tt + 1], z = ct[3 * tt + 2];
            atomicMax(&g_win_tgt[(x * DIM + y) * DIM + z], n_g + tt);
        }
    }
}

// Global rows, 2 per thread: bounds test, visibility gather, emit
// valid/near_mask, record packed winner (row<<1 | row_any_nonzero).
__global__ void k_scatter_glb(const int* __restrict__ gc,
                              const float4* __restrict__ glb_vals,
                              const int* __restrict__ origin,
                              float* __restrict__ out_valid,
                              float* __restrict__ out_near,
                              int n) {
    const int half = (n + 1) / 2;
    const int t = blockIdx.x * blockDim.x + threadIdx.x;
    const int ox = origin[0], oy = origin[1], oz = origin[2];
    #pragma unroll
    for (int k = 0; k < 2; ++k) {
        int i = t + k * half;
        if (i >= n) break;
        int x = gc[3 * i]     - ox;
        int y = gc[3 * i + 1] - oy;
        int z = gc[3 * i + 2] - oz;
        bool inb = ((unsigned)x < DIM) && ((unsigned)y < DIM) && ((unsigned)z < DIM);
        bool valid = false;
        if (inb) {
            int v = (x * DIM + y) * DIM + z;
            valid = (g_valid_vol[v] != 0);
            if (valid) {
                bool nz = false;
                #pragma unroll
                for (int q = 0; q < CH4; ++q) {
                    float4 r = glb_vals[i * CH4 + q];
                    nz |= (r.x != 0.0f) | (r.y != 0.0f) | (r.z != 0.0f) | (r.w != 0.0f);
                }
                atomicMax(&g_win_cg[v].y, (i << 1) | (nz ? 1 : 0));
            }
        }
        out_valid[i] = valid ? 1.0f : 0.0f;
        out_near[i]  = (inb && !valid) ? 1.0f : 0.0f;
    }
}

// Fused dense fill (byte-identical to R8 best). Misc blocks FIRST (no ragged
// tail), vectorized 4 voxels/thread. Fill blocks: 4-way ILP over grid-strided
// float4 slices; one LDG.64 fetches both winners per element; __stcs
// streaming stores keep tables/winners L2-resident (output write-once).
__global__ void k_fill(const float4* __restrict__ cur_vals,
                       const float4* __restrict__ glb_vals,
                       const float* __restrict__ tsdf_tgt,
                       const float* __restrict__ gtsdf_tgt,
                       float4* __restrict__ out_cur,
                       float4* __restrict__ out_glb,
                       float4* __restrict__ out_tgt,
                       float4* __restrict__ out_mask,
                       int n_gtgt) {
    int b = blockIdx.x;
    if (b >= MISC_BLOCKS) {
        int base = (b - MISC_BLOCKS) * B + threadIdx.x;
        const float4 zero = make_float4(0.f, 0.f, 0.f, 0.f);
        int e[FILL_ILP];
        int2 w[FILL_ILP];
        #pragma unroll
        for (int k = 0; k < FILL_ILP; ++k) {
            e[k] = base + k * FILL_THREADS;
            w[k] = g_win_cg[e[k] / CH4];
        }
        #pragma unroll
        for (int k = 0; k < FILL_ILP; ++k) {
            int v = e[k] / CH4;
            int q = e[k] - v * CH4;
            float4 rc = (w[k].x >= 0) ? cur_vals[w[k].x * CH4 + q] : zero;
            float4 rg = (w[k].y >= 0) ? glb_vals[(w[k].y >> 1) * CH4 + q] : zero;
            __stcs(&out_cur[e[k]], rc);
            __stcs(&out_glb[e[k]], rg);
        }
        return;
    }
    // misc: 4 voxels per thread; int4 loads cover 2 packed winner pairs each
    int t4 = b * B + threadIdx.x;            // float4 index into out_tgt/out_mask
    int4 wt = ((const int4*)g_win_tgt)[t4];
    int4 wp0 = ((const int4*)g_win_cg)[t4 * 2 + 0];   // voxels v0,v0+1: (cur,glb,cur,glb)
    int4 wp1 = ((const int4*)g_win_cg)[t4 * 2 + 1];   // voxels v0+2,v0+3
    unsigned int occ4 = ((const unsigned int*)g_occ)[t4];

    float tv[4];
    int wts[4] = {wt.x, wt.y, wt.z, wt.w};
    #pragma unroll
    for (int k = 0; k < 4; ++k) {
        int w = wts[k];
        if (w < 0)            tv[k] = 1.0f;
        else if (w >= n_gtgt) tv[k] = tsdf_tgt[w - n_gtgt];
        else                  tv[k] = gtsdf_tgt[w];
    }
    __stcs(&out_tgt[t4], make_float4(tv[0], tv[1], tv[2], tv[3]));

    int wgs[4] = {wp0.y, wp0.w, wp1.y, wp1.w};
    float mv[4];
    #pragma unroll
    for (int k = 0; k < 4; ++k) {
        bool m = ((occ4 >> (8 * k)) & 0xFF) != 0;
        m |= (wgs[k] >= 0) && (wgs[k] & 1);
        mv[k] = m ? 1.0f : 0.0f;
    }
    __stcs(&out_mask[t4], make_float4(mv[0], mv[1], mv[2], mv[3]));
}

// ---------------- launch ----------------

extern "C" void kernel_launch(void* const* d_in, const int* in_sizes, int n_in,
                              void* d_out, int out_size) {
    const int*   cur_coords = (const int*)d_in[0];
    const float* cur_vals   = (const float*)d_in[1];
    const int*   glb_coords = (const int*)d_in[2];
    const float* glb_vals   = (const float*)d_in[3];
    const int*   ct_coords  = (const int*)d_in[4];
    const float* tsdf_tgt   = (const float*)d_in[5];
    const int*   gct_coords = (const int*)d_in[6];
    const float* gtsdf_tgt  = (const float*)d_in[7];
    const int*   origin     = (const int*)d_in[8];
    const int*   grid_mask  = (const int*)d_in[9];   // bool promoted to 4-byte
    const int*   occupancy  = (const int*)d_in[10];  // bool promoted to 4-byte

    const int n_cur  = in_sizes[0] / 3;
    const int n_glb  = in_sizes[2] / 3;
    const int n_tgt  = in_sizes[4] / 3;
    const int n_gtgt = in_sizes[6] / 3;

    float* out = (float*)d_out;
    // output layout: tuple order, flattened, float32
    float* out_mask  = out;                          // DIM3
    float* out_cur   = out_mask + DIM3;              // DIM3*CH
    float* out_glb   = out_cur + (size_t)DIM3 * CH;  // DIM3*CH
    float* out_tgt   = out_glb + (size_t)DIM3 * CH;  // DIM3
    float* out_valid = out_tgt + DIM3;               // n_glb
    float* out_vt    = out_valid + n_glb;            // n_gtgt
    float* out_near  = out_vt + n_gtgt;              // n_glb

    k_init<<<(DIM3 / 2 + B - 1) / B, B>>>();

    int n_a = n_cur + n_gtgt + n_tgt;
    int half_a = (n_a + 1) / 2;
    k_scatter_a<<<(half_a + B - 1) / B, B>>>(cur_coords, grid_mask, occupancy,
                                             gct_coords, ct_coords, origin,
                                             out_vt, n_cur, n_gtgt, n_tgt);

    int half_g = (n_glb + 1) / 2;
    k_scatter_glb<<<(half_g + B - 1) / B, B>>>(glb_coords, (const float4*)glb_vals,
                                               origin, out_valid, out_near, n_glb);

    k_fill<<<MISC_BLOCKS + FILL_BLOCKS, B>>>((const float4*)cur_vals, (const float4*)glb_vals,
                                             tsdf_tgt, gtsdf_tgt,
                                             (float4*)out_cur, (float4*)out_glb,
                                             (float4*)out_tgt, (float4*)out_mask, n_gtgt);
}